// round 8
// baseline (speedup 1.0000x reference)
#include <cuda_runtime.h>
#include <cstdint>
#include <cstddef>

typedef unsigned long long u64;
#define DEVINL __device__ __forceinline__

// ---------- packed f32x2 helpers ----------
DEVINL u64 dup2(float v) { u64 r; asm("mov.b64 %0, {%1, %1};" : "=l"(r) : "f"(v)); return r; }
DEVINL float2 u2f(u64 v) { float2 f; asm("mov.b64 {%0, %1}, %2;" : "=f"(f.x), "=f"(f.y) : "l"(v)); return f; }
DEVINL void fma2(u64& d, u64 a, u64 b) { asm("fma.rn.f32x2 %0, %1, %2, %0;" : "+l"(d) : "l"(a), "l"(b)); }
DEVINL u64 mul2(u64 a, u64 b) { u64 d; asm("mul.rn.f32x2 %0, %1, %2;" : "=l"(d) : "l"(a), "l"(b)); return d; }

// ---------- cp.async helpers ----------
DEVINL void cpasync16(void* smem_dst, const void* gmem_src) {
    unsigned s = (unsigned)__cvta_generic_to_shared(smem_dst);
    asm volatile("cp.async.cg.shared.global [%0], [%1], 16;" :: "r"(s), "l"(gmem_src));
}
DEVINL void cp_commit() { asm volatile("cp.async.commit_group;"); }
DEVINL void cp_wait0()  { asm volatile("cp.async.wait_group 0;"); }

DEVINL float red16max(float v) {
    v = fmaxf(v, __shfl_xor_sync(0xffffffffu, v, 1));
    v = fmaxf(v, __shfl_xor_sync(0xffffffffu, v, 2));
    v = fmaxf(v, __shfl_xor_sync(0xffffffffu, v, 4));
    v = fmaxf(v, __shfl_xor_sync(0xffffffffu, v, 8));
    return v;
}
DEVINL float red16sum(float v) {
    v += __shfl_xor_sync(0xffffffffu, v, 1);
    v += __shfl_xor_sync(0xffffffffu, v, 2);
    v += __shfl_xor_sync(0xffffffffu, v, 4);
    v += __shfl_xor_sync(0xffffffffu, v, 8);
    return v;
}

// B=8, C=512, N=1024 tokens, heads=4, d_k=128, M=8192 tokens total
__device__ float g_qkv[8192ull * 1536ull];   // [token][h*384 + {q:0,k:128,v:256} + d]
__device__ float g_attT[512ull * 8192ull];   // transposed attn out: [c = h*128+d][token]

// ============================================================================
// Kernel 1: qkv = xs @ Wp + bp.  xs[m][c] = x[b][c][pos] (x layout = A^T, free)
// 128x128x16 tiles, cp.async double-buffered, one barrier per k-tile.
// ============================================================================
__global__ void __launch_bounds__(256) qkv_kernel(const float* __restrict__ x,
                                                  const float* __restrict__ Wp,
                                                  const float* __restrict__ bp) {
    __shared__ float As[2][16][128];
    __shared__ float Bs[2][16][128];
    const int tid = threadIdx.x;
    const int tx = tid & 15, ty = tid >> 4;
    const int m0 = blockIdx.y * 128;
    const int n0 = blockIdx.x * 128;
    const int b = m0 >> 10;
    const int pos0 = m0 & 1023;
    const float* xb = x + (size_t)b * (512 * 1024) + pos0;

    const int kkL = tid >> 5, q4L = tid & 31;       // slot 0
    const int kkH = kkL + 8;                        // slot 1 (it=1)

    u64 acc[8][4];
#pragma unroll
    for (int i = 0; i < 8; i++)
#pragma unroll
        for (int j = 0; j < 4; j++) acc[i][j] = 0ull;

    // preload k-tile 0
    cpasync16(&As[0][kkL][q4L * 4], xb + (size_t)kkL * 1024 + q4L * 4);
    cpasync16(&Bs[0][kkL][q4L * 4], Wp + (size_t)kkL * 1536 + n0 + q4L * 4);
    cpasync16(&As[0][kkH][q4L * 4], xb + (size_t)kkH * 1024 + q4L * 4);
    cpasync16(&Bs[0][kkH][q4L * 4], Wp + (size_t)kkH * 1536 + n0 + q4L * 4);
    cp_commit();

    int buf = 0;
    for (int k0 = 0; k0 < 512; k0 += 16) {
        cp_wait0();
        __syncthreads();
        if (k0 + 16 < 512) {
            int kn = k0 + 16;
            cpasync16(&As[buf ^ 1][kkL][q4L * 4], xb + (size_t)(kn + kkL) * 1024 + q4L * 4);
            cpasync16(&Bs[buf ^ 1][kkL][q4L * 4], Wp + (size_t)(kn + kkL) * 1536 + n0 + q4L * 4);
            cpasync16(&As[buf ^ 1][kkH][q4L * 4], xb + (size_t)(kn + kkH) * 1024 + q4L * 4);
            cpasync16(&Bs[buf ^ 1][kkH][q4L * 4], Wp + (size_t)(kn + kkH) * 1536 + n0 + q4L * 4);
            cp_commit();
        }
#pragma unroll
        for (int kk = 0; kk < 16; kk++) {
            float4 a0 = *(const float4*)&As[buf][kk][ty * 4];
            float4 a1 = *(const float4*)&As[buf][kk][64 + ty * 4];
            ulonglong2 b0 = *(const ulonglong2*)&Bs[buf][kk][tx * 4];
            ulonglong2 b1 = *(const ulonglong2*)&Bs[buf][kk][64 + tx * 4];
            float am[8] = {a0.x, a0.y, a0.z, a0.w, a1.x, a1.y, a1.z, a1.w};
#pragma unroll
            for (int i = 0; i < 8; i++) {
                u64 ad = dup2(am[i]);
                fma2(acc[i][0], ad, b0.x);
                fma2(acc[i][1], ad, b0.y);
                fma2(acc[i][2], ad, b1.x);
                fma2(acc[i][3], ad, b1.y);
            }
        }
        buf ^= 1;
    }
    float4 bias0 = *(const float4*)(bp + n0 + tx * 4);
    float4 bias1 = *(const float4*)(bp + n0 + 64 + tx * 4);
#pragma unroll
    for (int i = 0; i < 8; i++) {
        int m = m0 + ((i < 4) ? (ty * 4 + i) : (64 + ty * 4 + i - 4));
        float* orow = g_qkv + (size_t)m * 1536 + n0;
        float2 p0 = u2f(acc[i][0]), p1 = u2f(acc[i][1]);
        float2 p2 = u2f(acc[i][2]), p3 = u2f(acc[i][3]);
        *(float4*)(orow + tx * 4) =
            make_float4(p0.x + bias0.x, p0.y + bias0.y, p1.x + bias0.z, p1.y + bias0.w);
        *(float4*)(orow + 64 + tx * 4) =
            make_float4(p2.x + bias1.x, p2.y + bias1.y, p3.x + bias1.z, p3.y + bias1.w);
    }
}

// ============================================================================
// Kernel 2: flash attention per (b,h). 64 q x 64 k tiles, D=128, 256 threads.
// 2 CTAs/SM (224KB smem total). Swizzle group hoisted out of inner loops.
// V loaded via cp.async (natural layout); K transposed+swizzled via LDG/STS.
// ============================================================================
#define ATTN_SMEM (28672 * 4)

__global__ void __launch_bounds__(256, 2) attn_kernel() {
    extern __shared__ float sm[];
    float* Qs = sm;              // [128][64] swizzled: Qs[d*64 + (r ^ 2*(d>>2))]
    float* Ks = sm + 8192;       // [128][64] swizzled
    float* Vs = sm + 16384;      // [64][128] natural
    float* Ps = sm + 24576;      // [64][64]  swizzled: Ps[c*64 + (r ^ 2*(c>>2))]
    const int tid = threadIdx.x;
    const int tx = tid & 15, ty = tid >> 4;
    const int qt = blockIdx.x, h = blockIdx.y, b = blockIdx.z;
    const int tok0 = b * 1024 + qt * 64;
    const float scale = 0.08838834764831845f;  // 128^-0.5

#pragma unroll
    for (int it = 0; it < 8; it++) {
        int slot = it * 256 + tid;
        int row = slot >> 5, d4 = slot & 31;
        float4 qv = *(const float4*)(g_qkv + (size_t)(tok0 + row) * 1536 + h * 384 + d4 * 4);
        int sc = row ^ (d4 * 2);
        int base = d4 * 4 * 64;
        Qs[base + sc]       = qv.x * scale;
        Qs[base + 64 + sc]  = qv.y * scale;
        Qs[base + 128 + sc] = qv.z * scale;
        Qs[base + 192 + sc] = qv.w * scale;
    }

    u64 racc[4][4];
#pragma unroll
    for (int i = 0; i < 4; i++)
#pragma unroll
        for (int j = 0; j < 4; j++) racc[i][j] = 0ull;
    float rmax[4] = {-1e30f, -1e30f, -1e30f, -1e30f};
    float rsum[4] = {0.f, 0.f, 0.f, 0.f};

    for (int kt = 0; kt < 16; kt++) {
        __syncthreads();  // prev PV done (and Q ready on iter 0)
        const int kbase = b * 1024 + kt * 64;
#pragma unroll
        for (int it = 0; it < 8; it++) {
            int slot = it * 256 + tid;
            int row = slot >> 5, d4 = slot & 31;
            const float* src = g_qkv + (size_t)(kbase + row) * 1536 + h * 384 + d4 * 4;
            cpasync16(&Vs[row * 128 + d4 * 4], src + 256);
            float4 kv = *(const float4*)(src + 128);
            int sc = row ^ (d4 * 2);
            int base = d4 * 4 * 64;
            Ks[base + sc]       = kv.x;
            Ks[base + 64 + sc]  = kv.y;
            Ks[base + 128 + sc] = kv.z;
            Ks[base + 192 + sc] = kv.w;
        }
        cp_commit();
        cp_wait0();
        __syncthreads();

        // S[64x64] = Q K^T (pre-scaled); swizzle group g constant per 4 d's.
        u64 sp[4][2];
#pragma unroll
        for (int i = 0; i < 4; i++) { sp[i][0] = 0ull; sp[i][1] = 0ull; }
#pragma unroll 2
        for (int dg = 0; dg < 32; dg++) {
            const int g = dg * 2;
            const float* qrow = Qs + dg * 256;
            const float* krow = Ks + dg * 256;
            const int oq0 = (2 * ty) ^ g, oq1 = (32 + 2 * ty) ^ g;
            const int ok0 = (2 * tx) ^ g, ok1 = (32 + 2 * tx) ^ g;
#pragma unroll
            for (int dd = 0; dd < 4; dd++) {
                float2 qa0 = *(const float2*)(qrow + dd * 64 + oq0);
                float2 qa1 = *(const float2*)(qrow + dd * 64 + oq1);
                u64 kb0 = *(const u64*)(krow + dd * 64 + ok0);
                u64 kb1 = *(const u64*)(krow + dd * 64 + ok1);
                u64 a;
                a = dup2(qa0.x); fma2(sp[0][0], a, kb0); fma2(sp[0][1], a, kb1);
                a = dup2(qa0.y); fma2(sp[1][0], a, kb0); fma2(sp[1][1], a, kb1);
                a = dup2(qa1.x); fma2(sp[2][0], a, kb0); fma2(sp[2][1], a, kb1);
                a = dup2(qa1.y); fma2(sp[3][0], a, kb0); fma2(sp[3][1], a, kb1);
            }
        }

        // online softmax + write P transposed
        const int cols[4] = {2 * tx, 2 * tx + 1, 32 + 2 * tx, 33 + 2 * tx};
        const int rows[4] = {2 * ty, 2 * ty + 1, 32 + 2 * ty, 33 + 2 * ty};
#pragma unroll
        for (int i = 0; i < 4; i++) {
            float2 p0 = u2f(sp[i][0]), p1 = u2f(sp[i][1]);
            float s0 = p0.x, s1 = p0.y, s2 = p1.x, s3 = p1.y;
            float tmax = red16max(fmaxf(fmaxf(s0, s1), fmaxf(s2, s3)));
            float mnew = fmaxf(rmax[i], tmax);
            float corr = __expf(rmax[i] - mnew);
            rmax[i] = mnew;
            float e0 = __expf(s0 - mnew), e1 = __expf(s1 - mnew);
            float e2 = __expf(s2 - mnew), e3 = __expf(s3 - mnew);
            rsum[i] = rsum[i] * corr + red16sum(e0 + e1 + e2 + e3);
            u64 c2 = dup2(corr);
            racc[i][0] = mul2(racc[i][0], c2);
            racc[i][1] = mul2(racc[i][1], c2);
            racc[i][2] = mul2(racc[i][2], c2);
            racc[i][3] = mul2(racc[i][3], c2);
            int r = rows[i];
            Ps[cols[0] * 64 + (r ^ ((cols[0] >> 2) << 1))] = e0;
            Ps[cols[1] * 64 + (r ^ ((cols[1] >> 2) << 1))] = e1;
            Ps[cols[2] * 64 + (r ^ ((cols[2] >> 2) << 1))] = e2;
            Ps[cols[3] * 64 + (r ^ ((cols[3] >> 2) << 1))] = e3;
        }
        __syncthreads();

        // O[64x128] += P V ; swizzle group g constant per 4 j's.
#pragma unroll 2
        for (int jg = 0; jg < 16; jg++) {
            const int g = jg * 2;
            const float* prow = Ps + jg * 256;
            const float* vrow = Vs + jg * 512 + tx * 4;
            const int op0 = (2 * ty) ^ g, op1 = (32 + 2 * ty) ^ g;
#pragma unroll
            for (int jj = 0; jj < 4; jj++) {
                float2 pa0 = *(const float2*)(prow + jj * 64 + op0);
                float2 pa1 = *(const float2*)(prow + jj * 64 + op1);
                ulonglong2 v0 = *(const ulonglong2*)(vrow + jj * 128);
                ulonglong2 v1 = *(const ulonglong2*)(vrow + jj * 128 + 64);
                u64 a;
                a = dup2(pa0.x); fma2(racc[0][0], a, v0.x); fma2(racc[0][1], a, v0.y);
                                 fma2(racc[0][2], a, v1.x); fma2(racc[0][3], a, v1.y);
                a = dup2(pa0.y); fma2(racc[1][0], a, v0.x); fma2(racc[1][1], a, v0.y);
                                 fma2(racc[1][2], a, v1.x); fma2(racc[1][3], a, v1.y);
                a = dup2(pa1.x); fma2(racc[2][0], a, v0.x); fma2(racc[2][1], a, v0.y);
                                 fma2(racc[2][2], a, v1.x); fma2(racc[2][3], a, v1.y);
                a = dup2(pa1.y); fma2(racc[3][0], a, v0.x); fma2(racc[3][1], a, v0.y);
                                 fma2(racc[3][2], a, v1.x); fma2(racc[3][3], a, v1.y);
            }
        }
    }

    // normalize + write transposed: g_attT[(h*128+d)*8192 + token], float2 pairs
    float inv0 = 1.0f / rsum[0], inv1 = 1.0f / rsum[1];
    float inv2 = 1.0f / rsum[2], inv3 = 1.0f / rsum[3];
#pragma unroll
    for (int j = 0; j < 4; j++) {
        int d0 = (j < 2) ? (tx * 4 + j * 2) : (64 + tx * 4 + (j - 2) * 2);
        float2 a = u2f(racc[0][j]);  // row 2ty,    d0 / d0+1
        float2 c = u2f(racc[1][j]);  // row 2ty+1
        float2 e = u2f(racc[2][j]);  // row 32+2ty
        float2 f = u2f(racc[3][j]);  // row 33+2ty
        size_t base0 = (size_t)(h * 128 + d0) * 8192 + tok0;
        size_t base1 = base0 + 8192;
        *(float2*)(g_attT + base0 + 2 * ty)      = make_float2(a.x * inv0, c.x * inv1);
        *(float2*)(g_attT + base1 + 2 * ty)      = make_float2(a.y * inv0, c.y * inv1);
        *(float2*)(g_attT + base0 + 32 + 2 * ty) = make_float2(e.x * inv2, f.x * inv3);
        *(float2*)(g_attT + base1 + 32 + 2 * ty) = make_float2(e.y * inv2, f.y * inv3);
    }
}

// ============================================================================
// Kernel 3: out[b][c][pos] = (attn @ Wo)[m][c] + bo[c] + xs[m][c], computed as
// C^T[c][tok]; cp.async double-buffered like kernel 1.
// ============================================================================
__global__ void __launch_bounds__(256) out_kernel(const float* __restrict__ x,
                                                  const float* __restrict__ Wo,
                                                  const float* __restrict__ bo,
                                                  float* __restrict__ out) {
    __shared__ float As[2][16][128];  // Wo[k][c] slice (contiguous in c)
    __shared__ float Bs[2][16][128];  // g_attT[k][tok] slice (contiguous in tok)
    const int tid = threadIdx.x;
    const int tx = tid & 15, ty = tid >> 4;
    const int c0 = blockIdx.x * 128;
    const int m0 = blockIdx.y * 128;
    const int b = m0 >> 10;
    const int pos0 = m0 & 1023;

    const int kkL = tid >> 5, q4L = tid & 31;
    const int kkH = kkL + 8;

    u64 acc[8][4];
#pragma unroll
    for (int i = 0; i < 8; i++)
#pragma unroll
        for (int j = 0; j < 4; j++) acc[i][j] = 0ull;

    cpasync16(&As[0][kkL][q4L * 4], Wo + (size_t)kkL * 512 + c0 + q4L * 4);
    cpasync16(&Bs[0][kkL][q4L * 4], g_attT + (size_t)kkL * 8192 + m0 + q4L * 4);
    cpasync16(&As[0][kkH][q4L * 4], Wo + (size_t)kkH * 512 + c0 + q4L * 4);
    cpasync16(&Bs[0][kkH][q4L * 4], g_attT + (size_t)kkH * 8192 + m0 + q4L * 4);
    cp_commit();

    int buf = 0;
    for (int k0 = 0; k0 < 512; k0 += 16) {
        cp_wait0();
        __syncthreads();
        if (k0 + 16 < 512) {
            int kn = k0 + 16;
            cpasync16(&As[buf ^ 1][kkL][q4L * 4], Wo + (size_t)(kn + kkL) * 512 + c0 + q4L * 4);
            cpasync16(&Bs[buf ^ 1][kkL][q4L * 4], g_attT + (size_t)(kn + kkL) * 8192 + m0 + q4L * 4);
            cpasync16(&As[buf ^ 1][kkH][q4L * 4], Wo + (size_t)(kn + kkH) * 512 + c0 + q4L * 4);
            cpasync16(&Bs[buf ^ 1][kkH][q4L * 4], g_attT + (size_t)(kn + kkH) * 8192 + m0 + q4L * 4);
            cp_commit();
        }
#pragma unroll
        for (int kk = 0; kk < 16; kk++) {
            float4 a0 = *(const float4*)&As[buf][kk][ty * 4];
            float4 a1 = *(const float4*)&As[buf][kk][64 + ty * 4];
            ulonglong2 b0 = *(const ulonglong2*)&Bs[buf][kk][tx * 4];
            ulonglong2 b1 = *(const ulonglong2*)&Bs[buf][kk][64 + tx * 4];
            float am[8] = {a0.x, a0.y, a0.z, a0.w, a1.x, a1.y, a1.z, a1.w};
#pragma unroll
            for (int i = 0; i < 8; i++) {
                u64 ad = dup2(am[i]);
                fma2(acc[i][0], ad, b0.x);
                fma2(acc[i][1], ad, b0.y);
                fma2(acc[i][2], ad, b1.x);
                fma2(acc[i][3], ad, b1.y);
            }
        }
        buf ^= 1;
    }
#pragma unroll
    for (int i = 0; i < 8; i++) {
        int c = c0 + ((i < 4) ? (ty * 4 + i) : (64 + ty * 4 + i - 4));
        float bb = bo[c];
        const float* xr = x + ((size_t)b * 512 + c) * 1024 + pos0;
        float* orow = out + ((size_t)b * 512 + c) * 1024 + pos0;
        float4 r0 = *(const float4*)(xr + tx * 4);
        float4 r1 = *(const float4*)(xr + 64 + tx * 4);
        float2 p0 = u2f(acc[i][0]), p1 = u2f(acc[i][1]);
        float2 p2 = u2f(acc[i][2]), p3 = u2f(acc[i][3]);
        *(float4*)(orow + tx * 4) =
            make_float4(p0.x + bb + r0.x, p0.y + bb + r0.y, p1.x + bb + r0.z, p1.y + bb + r0.w);
        *(float4*)(orow + 64 + tx * 4) =
            make_float4(p2.x + bb + r1.x, p2.y + bb + r1.y, p3.x + bb + r1.z, p3.y + bb + r1.w);
    }
}

extern "C" void kernel_launch(void* const* d_in, const int* in_sizes, int n_in,
                              void* d_out, int out_size) {
    const float* x  = (const float*)d_in[0];
    const float* Wp = (const float*)d_in[1];
    const float* bp = (const float*)d_in[2];
    const float* Wo = (const float*)d_in[3];
    const float* bo = (const float*)d_in[4];
    float* out = (float*)d_out;

    static bool attr_set = false;
    if (!attr_set) {
        cudaFuncSetAttribute(attn_kernel, cudaFuncAttributeMaxDynamicSharedMemorySize, ATTN_SMEM);
        attr_set = true;
    }

    qkv_kernel<<<dim3(12, 64), 256>>>(x, Wp, bp);
    attn_kernel<<<dim3(16, 4, 8), 256, ATTN_SMEM>>>();
    out_kernel<<<dim3(4, 64), 256>>>(x, Wo, bo, out);
}

// round 9
// speedup vs baseline: 1.5676x; 1.5676x over previous
#include <cuda_runtime.h>
#include <cstdint>
#include <cstddef>

typedef unsigned long long u64;
#define DEVINL __device__ __forceinline__

// ---------- packed f32x2 helpers ----------
DEVINL u64 dup2(float v) { u64 r; asm("mov.b64 %0, {%1, %1};" : "=l"(r) : "f"(v)); return r; }
DEVINL float2 u2f(u64 v) { float2 f; asm("mov.b64 {%0, %1}, %2;" : "=f"(f.x), "=f"(f.y) : "l"(v)); return f; }
DEVINL void fma2(u64& d, u64 a, u64 b) { asm("fma.rn.f32x2 %0, %1, %2, %0;" : "+l"(d) : "l"(a), "l"(b)); }
DEVINL u64 mul2(u64 a, u64 b) { u64 d; asm("mul.rn.f32x2 %0, %1, %2;" : "=l"(d) : "l"(a), "l"(b)); return d; }

DEVINL float red16max(float v) {
    v = fmaxf(v, __shfl_xor_sync(0xffffffffu, v, 1));
    v = fmaxf(v, __shfl_xor_sync(0xffffffffu, v, 2));
    v = fmaxf(v, __shfl_xor_sync(0xffffffffu, v, 4));
    v = fmaxf(v, __shfl_xor_sync(0xffffffffu, v, 8));
    return v;
}
DEVINL float red16sum(float v) {
    v += __shfl_xor_sync(0xffffffffu, v, 1);
    v += __shfl_xor_sync(0xffffffffu, v, 2);
    v += __shfl_xor_sync(0xffffffffu, v, 4);
    v += __shfl_xor_sync(0xffffffffu, v, 8);
    return v;
}

// B=8, C=512, N=1024 tokens, heads=4, d_k=128, M=8192 tokens total
__device__ float g_qkv[8192ull * 1536ull];   // [token][h*384 + {q:0,k:128,v:256} + d]
__device__ float g_attT[512ull * 8192ull];   // transposed attn out: [c = h*128+d][token]

// ============================================================================
// Kernel 1: qkv = xs @ Wp + bp.  xs[m][c] = x[b][c][pos] (x layout = A^T, free)
// 128x128x16 tiles (R6-proven LDG/STS path), minBlocks=2 for 2 resident CTAs.
// ============================================================================
__global__ void __launch_bounds__(256, 2) qkv_kernel(const float* __restrict__ x,
                                                     const float* __restrict__ Wp,
                                                     const float* __restrict__ bp) {
    __shared__ float As[16][128];
    __shared__ float Bs[16][128];
    const int tid = threadIdx.x;
    const int tx = tid & 15, ty = tid >> 4;
    const int m0 = blockIdx.y * 128;
    const int n0 = blockIdx.x * 128;
    const int b = m0 >> 10;
    const int pos0 = m0 & 1023;
    const float* xb = x + (size_t)b * (512 * 1024) + pos0;

    u64 acc[8][4];
#pragma unroll
    for (int i = 0; i < 8; i++)
#pragma unroll
        for (int j = 0; j < 4; j++) acc[i][j] = 0ull;

    for (int k0 = 0; k0 < 512; k0 += 16) {
        __syncthreads();
#pragma unroll
        for (int it = 0; it < 2; it++) {
            int slot = it * 256 + tid;
            int kk = slot >> 5, q4 = slot & 31;
            *(float4*)&As[kk][q4 * 4] = *(const float4*)(xb + (size_t)(k0 + kk) * 1024 + q4 * 4);
            *(float4*)&Bs[kk][q4 * 4] = *(const float4*)(Wp + (size_t)(k0 + kk) * 1536 + n0 + q4 * 4);
        }
        __syncthreads();
#pragma unroll
        for (int kk = 0; kk < 16; kk++) {
            float4 a0 = *(const float4*)&As[kk][ty * 4];
            float4 a1 = *(const float4*)&As[kk][64 + ty * 4];
            ulonglong2 b0 = *(const ulonglong2*)&Bs[kk][tx * 4];
            ulonglong2 b1 = *(const ulonglong2*)&Bs[kk][64 + tx * 4];
            float am[8] = {a0.x, a0.y, a0.z, a0.w, a1.x, a1.y, a1.z, a1.w};
#pragma unroll
            for (int i = 0; i < 8; i++) {
                u64 ad = dup2(am[i]);
                fma2(acc[i][0], ad, b0.x);
                fma2(acc[i][1], ad, b0.y);
                fma2(acc[i][2], ad, b1.x);
                fma2(acc[i][3], ad, b1.y);
            }
        }
    }
    float4 bias0 = *(const float4*)(bp + n0 + tx * 4);
    float4 bias1 = *(const float4*)(bp + n0 + 64 + tx * 4);
#pragma unroll
    for (int i = 0; i < 8; i++) {
        int m = m0 + ((i < 4) ? (ty * 4 + i) : (64 + ty * 4 + i - 4));
        float* orow = g_qkv + (size_t)m * 1536 + n0;
        float2 p0 = u2f(acc[i][0]), p1 = u2f(acc[i][1]);
        float2 p2 = u2f(acc[i][2]), p3 = u2f(acc[i][3]);
        *(float4*)(orow + tx * 4) =
            make_float4(p0.x + bias0.x, p0.y + bias0.y, p1.x + bias0.z, p1.y + bias0.w);
        *(float4*)(orow + 64 + tx * 4) =
            make_float4(p2.x + bias1.x, p2.y + bias1.y, p3.x + bias1.z, p3.y + bias1.w);
    }
}

// ============================================================================
// Kernel 2: flash attention per (b,h). 64 q x 64 k tiles, D=128, 256 threads.
// R6 LDG/STS load path; 2 CTAs/SM (2x112KB = 224KB <= 228KB carveout).
// Swizzle group hoisted out of the S and PV inner loops (ALU issue reduction).
// ============================================================================
#define ATTN_SMEM (28672 * 4)

__global__ void __launch_bounds__(256, 2) attn_kernel() {
    extern __shared__ float sm[];
    float* Qs = sm;              // [128][64] swizzled: Qs[d*64 + (r ^ 2*(d>>2))]
    float* Ks = sm + 8192;       // [128][64] swizzled
    float* Vs = sm + 16384;      // [64][128] natural
    float* Ps = sm + 24576;      // [64][64]  swizzled: Ps[c*64 + (r ^ 2*(c>>2))]
    const int tid = threadIdx.x;
    const int tx = tid & 15, ty = tid >> 4;
    const int qt = blockIdx.x, h = blockIdx.y, b = blockIdx.z;
    const int tok0 = b * 1024 + qt * 64;
    const float scale = 0.08838834764831845f;  // 128^-0.5

#pragma unroll
    for (int it = 0; it < 8; it++) {
        int slot = it * 256 + tid;
        int row = slot >> 5, d4 = slot & 31;
        float4 qv = *(const float4*)(g_qkv + (size_t)(tok0 + row) * 1536 + h * 384 + d4 * 4);
        int sc = row ^ (d4 * 2);
        int base = d4 * 4 * 64;
        Qs[base + sc]       = qv.x * scale;
        Qs[base + 64 + sc]  = qv.y * scale;
        Qs[base + 128 + sc] = qv.z * scale;
        Qs[base + 192 + sc] = qv.w * scale;
    }

    u64 racc[4][4];
#pragma unroll
    for (int i = 0; i < 4; i++)
#pragma unroll
        for (int j = 0; j < 4; j++) racc[i][j] = 0ull;
    float rmax[4] = {-1e30f, -1e30f, -1e30f, -1e30f};
    float rsum[4] = {0.f, 0.f, 0.f, 0.f};

    for (int kt = 0; kt < 16; kt++) {
        __syncthreads();  // prev PV done (and Q ready on iter 0)
        const int kbase = b * 1024 + kt * 64;
#pragma unroll
        for (int it = 0; it < 8; it++) {
            int slot = it * 256 + tid;
            int row = slot >> 5, d4 = slot & 31;
            const float* src = g_qkv + (size_t)(kbase + row) * 1536 + h * 384 + d4 * 4;
            float4 kv = *(const float4*)(src + 128);
            float4 vv = *(const float4*)(src + 256);
            int sc = row ^ (d4 * 2);
            int base = d4 * 4 * 64;
            Ks[base + sc]       = kv.x;
            Ks[base + 64 + sc]  = kv.y;
            Ks[base + 128 + sc] = kv.z;
            Ks[base + 192 + sc] = kv.w;
            *(float4*)&Vs[row * 128 + d4 * 4] = vv;
        }
        __syncthreads();

        // S[64x64] = Q K^T (pre-scaled); swizzle group g constant per 4 d's.
        u64 sp[4][2];
#pragma unroll
        for (int i = 0; i < 4; i++) { sp[i][0] = 0ull; sp[i][1] = 0ull; }
#pragma unroll 2
        for (int dg = 0; dg < 32; dg++) {
            const int g = dg * 2;
            const float* qrow = Qs + dg * 256;
            const float* krow = Ks + dg * 256;
            const int oq0 = (2 * ty) ^ g, oq1 = (32 + 2 * ty) ^ g;
            const int ok0 = (2 * tx) ^ g, ok1 = (32 + 2 * tx) ^ g;
#pragma unroll
            for (int dd = 0; dd < 4; dd++) {
                float2 qa0 = *(const float2*)(qrow + dd * 64 + oq0);
                float2 qa1 = *(const float2*)(qrow + dd * 64 + oq1);
                u64 kb0 = *(const u64*)(krow + dd * 64 + ok0);
                u64 kb1 = *(const u64*)(krow + dd * 64 + ok1);
                u64 a;
                a = dup2(qa0.x); fma2(sp[0][0], a, kb0); fma2(sp[0][1], a, kb1);
                a = dup2(qa0.y); fma2(sp[1][0], a, kb0); fma2(sp[1][1], a, kb1);
                a = dup2(qa1.x); fma2(sp[2][0], a, kb0); fma2(sp[2][1], a, kb1);
                a = dup2(qa1.y); fma2(sp[3][0], a, kb0); fma2(sp[3][1], a, kb1);
            }
        }

        // online softmax + write P transposed
        const int cols[4] = {2 * tx, 2 * tx + 1, 32 + 2 * tx, 33 + 2 * tx};
        const int rows[4] = {2 * ty, 2 * ty + 1, 32 + 2 * ty, 33 + 2 * ty};
#pragma unroll
        for (int i = 0; i < 4; i++) {
            float2 p0 = u2f(sp[i][0]), p1 = u2f(sp[i][1]);
            float s0 = p0.x, s1 = p0.y, s2 = p1.x, s3 = p1.y;
            float tmax = red16max(fmaxf(fmaxf(s0, s1), fmaxf(s2, s3)));
            float mnew = fmaxf(rmax[i], tmax);
            float corr = __expf(rmax[i] - mnew);
            rmax[i] = mnew;
            float e0 = __expf(s0 - mnew), e1 = __expf(s1 - mnew);
            float e2 = __expf(s2 - mnew), e3 = __expf(s3 - mnew);
            rsum[i] = rsum[i] * corr + red16sum(e0 + e1 + e2 + e3);
            u64 c2 = dup2(corr);
            racc[i][0] = mul2(racc[i][0], c2);
            racc[i][1] = mul2(racc[i][1], c2);
            racc[i][2] = mul2(racc[i][2], c2);
            racc[i][3] = mul2(racc[i][3], c2);
            int r = rows[i];
            Ps[cols[0] * 64 + (r ^ ((cols[0] >> 2) << 1))] = e0;
            Ps[cols[1] * 64 + (r ^ ((cols[1] >> 2) << 1))] = e1;
            Ps[cols[2] * 64 + (r ^ ((cols[2] >> 2) << 1))] = e2;
            Ps[cols[3] * 64 + (r ^ ((cols[3] >> 2) << 1))] = e3;
        }
        __syncthreads();

        // O[64x128] += P V ; swizzle group g constant per 4 j's.
#pragma unroll 2
        for (int jg = 0; jg < 16; jg++) {
            const int g = jg * 2;
            const float* prow = Ps + jg * 256;
            const float* vrow = Vs + jg * 512 + tx * 4;
            const int op0 = (2 * ty) ^ g, op1 = (32 + 2 * ty) ^ g;
#pragma unroll
            for (int jj = 0; jj < 4; jj++) {
                float2 pa0 = *(const float2*)(prow + jj * 64 + op0);
                float2 pa1 = *(const float2*)(prow + jj * 64 + op1);
                ulonglong2 v0 = *(const ulonglong2*)(vrow + jj * 128);
                ulonglong2 v1 = *(const ulonglong2*)(vrow + jj * 128 + 64);
                u64 a;
                a = dup2(pa0.x); fma2(racc[0][0], a, v0.x); fma2(racc[0][1], a, v0.y);
                                 fma2(racc[0][2], a, v1.x); fma2(racc[0][3], a, v1.y);
                a = dup2(pa0.y); fma2(racc[1][0], a, v0.x); fma2(racc[1][1], a, v0.y);
                                 fma2(racc[1][2], a, v1.x); fma2(racc[1][3], a, v1.y);
                a = dup2(pa1.x); fma2(racc[2][0], a, v0.x); fma2(racc[2][1], a, v0.y);
                                 fma2(racc[2][2], a, v1.x); fma2(racc[2][3], a, v1.y);
                a = dup2(pa1.y); fma2(racc[3][0], a, v0.x); fma2(racc[3][1], a, v0.y);
                                 fma2(racc[3][2], a, v1.x); fma2(racc[3][3], a, v1.y);
            }
        }
    }

    // normalize + write transposed: g_attT[(h*128+d)*8192 + token], float2 pairs
    float inv0 = 1.0f / rsum[0], inv1 = 1.0f / rsum[1];
    float inv2 = 1.0f / rsum[2], inv3 = 1.0f / rsum[3];
#pragma unroll
    for (int j = 0; j < 4; j++) {
        int d0 = (j < 2) ? (tx * 4 + j * 2) : (64 + tx * 4 + (j - 2) * 2);
        float2 a = u2f(racc[0][j]);  // row 2ty,    d0 / d0+1
        float2 c = u2f(racc[1][j]);  // row 2ty+1
        float2 e = u2f(racc[2][j]);  // row 32+2ty
        float2 f = u2f(racc[3][j]);  // row 33+2ty
        size_t base0 = (size_t)(h * 128 + d0) * 8192 + tok0;
        size_t base1 = base0 + 8192;
        *(float2*)(g_attT + base0 + 2 * ty)      = make_float2(a.x * inv0, c.x * inv1);
        *(float2*)(g_attT + base1 + 2 * ty)      = make_float2(a.y * inv0, c.y * inv1);
        *(float2*)(g_attT + base0 + 32 + 2 * ty) = make_float2(e.x * inv2, f.x * inv3);
        *(float2*)(g_attT + base1 + 32 + 2 * ty) = make_float2(e.y * inv2, f.y * inv3);
    }
}

// ============================================================================
// Kernel 3: out[b][c][pos] = (attn @ Wo)[m][c] + bo[c] + xs[m][c], computed as
// C^T[c][tok]; R6-proven LDG/STS path, minBlocks=2.
// ============================================================================
__global__ void __launch_bounds__(256, 2) out_kernel(const float* __restrict__ x,
                                                     const float* __restrict__ Wo,
                                                     const float* __restrict__ bo,
                                                     float* __restrict__ out) {
    __shared__ float As[16][128];  // Wo[k][c] slice (contiguous in c)
    __shared__ float Bs[16][128];  // g_attT[k][tok] slice (contiguous in tok)
    const int tid = threadIdx.x;
    const int tx = tid & 15, ty = tid >> 4;
    const int c0 = blockIdx.x * 128;
    const int m0 = blockIdx.y * 128;
    const int b = m0 >> 10;
    const int pos0 = m0 & 1023;

    u64 acc[8][4];
#pragma unroll
    for (int i = 0; i < 8; i++)
#pragma unroll
        for (int j = 0; j < 4; j++) acc[i][j] = 0ull;

    for (int k0 = 0; k0 < 512; k0 += 16) {
        __syncthreads();
#pragma unroll
        for (int it = 0; it < 2; it++) {
            int slot = it * 256 + tid;
            int kk = slot >> 5, q4 = slot & 31;
            *(float4*)&As[kk][q4 * 4] = *(const float4*)(Wo + (size_t)(k0 + kk) * 512 + c0 + q4 * 4);
            *(float4*)&Bs[kk][q4 * 4] = *(const float4*)(g_attT + (size_t)(k0 + kk) * 8192 + m0 + q4 * 4);
        }
        __syncthreads();
#pragma unroll
        for (int kk = 0; kk < 16; kk++) {
            float4 a0 = *(const float4*)&As[kk][ty * 4];
            float4 a1 = *(const float4*)&As[kk][64 + ty * 4];
            ulonglong2 b0 = *(const ulonglong2*)&Bs[kk][tx * 4];
            ulonglong2 b1 = *(const ulonglong2*)&Bs[kk][64 + tx * 4];
            float am[8] = {a0.x, a0.y, a0.z, a0.w, a1.x, a1.y, a1.z, a1.w};
#pragma unroll
            for (int i = 0; i < 8; i++) {
                u64 ad = dup2(am[i]);
                fma2(acc[i][0], ad, b0.x);
                fma2(acc[i][1], ad, b0.y);
                fma2(acc[i][2], ad, b1.x);
                fma2(acc[i][3], ad, b1.y);
            }
        }
    }
#pragma unroll
    for (int i = 0; i < 8; i++) {
        int c = c0 + ((i < 4) ? (ty * 4 + i) : (64 + ty * 4 + i - 4));
        float bb = bo[c];
        const float* xr = x + ((size_t)b * 512 + c) * 1024 + pos0;
        float* orow = out + ((size_t)b * 512 + c) * 1024 + pos0;
        float4 r0 = *(const float4*)(xr + tx * 4);
        float4 r1 = *(const float4*)(xr + 64 + tx * 4);
        float2 p0 = u2f(acc[i][0]), p1 = u2f(acc[i][1]);
        float2 p2 = u2f(acc[i][2]), p3 = u2f(acc[i][3]);
        *(float4*)(orow + tx * 4) =
            make_float4(p0.x + bb + r0.x, p0.y + bb + r0.y, p1.x + bb + r0.z, p1.y + bb + r0.w);
        *(float4*)(orow + 64 + tx * 4) =
            make_float4(p2.x + bb + r1.x, p2.y + bb + r1.y, p3.x + bb + r1.z, p3.y + bb + r1.w);
    }
}

extern "C" void kernel_launch(void* const* d_in, const int* in_sizes, int n_in,
                              void* d_out, int out_size) {
    const float* x  = (const float*)d_in[0];
    const float* Wp = (const float*)d_in[1];
    const float* bp = (const float*)d_in[2];
    const float* Wo = (const float*)d_in[3];
    const float* bo = (const float*)d_in[4];
    float* out = (float*)d_out;

    static bool attr_set = false;
    if (!attr_set) {
        cudaFuncSetAttribute(attn_kernel, cudaFuncAttributeMaxDynamicSharedMemorySize, ATTN_SMEM);
        attr_set = true;
    }

    qkv_kernel<<<dim3(12, 64), 256>>>(x, Wp, bp);
    attn_kernel<<<dim3(16, 4, 8), 256, ATTN_SMEM>>>();
    out_kernel<<<dim3(4, 64), 256>>>(x, Wo, bo, out);
}

// round 11
// speedup vs baseline: 1.5687x; 1.0007x over previous
#include <cuda_runtime.h>
#include <cstdint>
#include <cstddef>

typedef unsigned long long u64;
#define DEVINL __device__ __forceinline__

// ---------- packed f32x2 helpers ----------
DEVINL u64 dup2(float v) { u64 r; asm("mov.b64 %0, {%1, %1};" : "=l"(r) : "f"(v)); return r; }
DEVINL float2 u2f(u64 v) { float2 f; asm("mov.b64 {%0, %1}, %2;" : "=f"(f.x), "=f"(f.y) : "l"(v)); return f; }
DEVINL void fma2(u64& d, u64 a, u64 b) { asm("fma.rn.f32x2 %0, %1, %2, %0;" : "+l"(d) : "l"(a), "l"(b)); }
DEVINL u64 mul2(u64 a, u64 b) { u64 d; asm("mul.rn.f32x2 %0, %1, %2;" : "=l"(d) : "l"(a), "l"(b)); return d; }

DEVINL float red16max(float v) {
    v = fmaxf(v, __shfl_xor_sync(0xffffffffu, v, 1));
    v = fmaxf(v, __shfl_xor_sync(0xffffffffu, v, 2));
    v = fmaxf(v, __shfl_xor_sync(0xffffffffu, v, 4));
    v = fmaxf(v, __shfl_xor_sync(0xffffffffu, v, 8));
    return v;
}
DEVINL float red16sum(float v) {
    v += __shfl_xor_sync(0xffffffffu, v, 1);
    v += __shfl_xor_sync(0xffffffffu, v, 2);
    v += __shfl_xor_sync(0xffffffffu, v, 4);
    v += __shfl_xor_sync(0xffffffffu, v, 8);
    return v;
}

// B=8, C=512, N=1024 tokens, heads=4, d_k=128, M=8192 tokens total
__device__ float g_qkv[8192ull * 1536ull];   // [token][h*384 + {q:0,k:128,v:256} + d]
__device__ float g_attT[512ull * 8192ull];   // transposed attn out: [c = h*128+d][token]

// ============================================================================
// Kernel 1: qkv = xs @ Wp + bp.  xs[m][c] = x[b][c][pos] (x layout = A^T, free)
// 128x128x16 tiles (R6-proven LDG/STS path), minBlocks=2 for 2 resident CTAs.
// ============================================================================
__global__ void __launch_bounds__(256, 2) qkv_kernel(const float* __restrict__ x,
                                                     const float* __restrict__ Wp,
                                                     const float* __restrict__ bp) {
    __shared__ float As[16][128];
    __shared__ float Bs[16][128];
    const int tid = threadIdx.x;
    const int tx = tid & 15, ty = tid >> 4;
    const int m0 = blockIdx.y * 128;
    const int n0 = blockIdx.x * 128;
    const int b = m0 >> 10;
    const int pos0 = m0 & 1023;
    const float* xb = x + (size_t)b * (512 * 1024) + pos0;

    u64 acc[8][4];
#pragma unroll
    for (int i = 0; i < 8; i++)
#pragma unroll
        for (int j = 0; j < 4; j++) acc[i][j] = 0ull;

    for (int k0 = 0; k0 < 512; k0 += 16) {
        __syncthreads();
#pragma unroll
        for (int it = 0; it < 2; it++) {
            int slot = it * 256 + tid;
            int kk = slot >> 5, q4 = slot & 31;
            *(float4*)&As[kk][q4 * 4] = *(const float4*)(xb + (size_t)(k0 + kk) * 1024 + q4 * 4);
            *(float4*)&Bs[kk][q4 * 4] = *(const float4*)(Wp + (size_t)(k0 + kk) * 1536 + n0 + q4 * 4);
        }
        __syncthreads();
#pragma unroll
        for (int kk = 0; kk < 16; kk++) {
            float4 a0 = *(const float4*)&As[kk][ty * 4];
            float4 a1 = *(const float4*)&As[kk][64 + ty * 4];
            ulonglong2 b0 = *(const ulonglong2*)&Bs[kk][tx * 4];
            ulonglong2 b1 = *(const ulonglong2*)&Bs[kk][64 + tx * 4];
            float am[8] = {a0.x, a0.y, a0.z, a0.w, a1.x, a1.y, a1.z, a1.w};
#pragma unroll
            for (int i = 0; i < 8; i++) {
                u64 ad = dup2(am[i]);
                fma2(acc[i][0], ad, b0.x);
                fma2(acc[i][1], ad, b0.y);
                fma2(acc[i][2], ad, b1.x);
                fma2(acc[i][3], ad, b1.y);
            }
        }
    }
    float4 bias0 = *(const float4*)(bp + n0 + tx * 4);
    float4 bias1 = *(const float4*)(bp + n0 + 64 + tx * 4);
#pragma unroll
    for (int i = 0; i < 8; i++) {
        int m = m0 + ((i < 4) ? (ty * 4 + i) : (64 + ty * 4 + i - 4));
        float* orow = g_qkv + (size_t)m * 1536 + n0;
        float2 p0 = u2f(acc[i][0]), p1 = u2f(acc[i][1]);
        float2 p2 = u2f(acc[i][2]), p3 = u2f(acc[i][3]);
        *(float4*)(orow + tx * 4) =
            make_float4(p0.x + bias0.x, p0.y + bias0.y, p1.x + bias0.z, p1.y + bias0.w);
        *(float4*)(orow + 64 + tx * 4) =
            make_float4(p2.x + bias1.x, p2.y + bias1.y, p3.x + bias1.z, p3.y + bias1.w);
    }
}

// ============================================================================
// Kernel 2: flash attention per (b,h). 64 q x 64 k tiles, D=128, 256 threads.
// R6 LDG/STS load path; 2 CTAs/SM (2x112KB = 224KB <= 228KB carveout).
// Swizzle group hoisted out of the S and PV inner loops (ALU issue reduction).
// ============================================================================
#define ATTN_SMEM (28672 * 4)

__global__ void __launch_bounds__(256, 2) attn_kernel() {
    extern __shared__ float sm[];
    float* Qs = sm;              // [128][64] swizzled: Qs[d*64 + (r ^ 2*(d>>2))]
    float* Ks = sm + 8192;       // [128][64] swizzled
    float* Vs = sm + 16384;      // [64][128] natural
    float* Ps = sm + 24576;      // [64][64]  swizzled: Ps[c*64 + (r ^ 2*(c>>2))]
    const int tid = threadIdx.x;
    const int tx = tid & 15, ty = tid >> 4;
    const int qt = blockIdx.x, h = blockIdx.y, b = blockIdx.z;
    const int tok0 = b * 1024 + qt * 64;
    const float scale = 0.08838834764831845f;  // 128^-0.5

#pragma unroll
    for (int it = 0; it < 8; it++) {
        int slot = it * 256 + tid;
        int row = slot >> 5, d4 = slot & 31;
        float4 qv = *(const float4*)(g_qkv + (size_t)(tok0 + row) * 1536 + h * 384 + d4 * 4);
        int sc = row ^ (d4 * 2);
        int base = d4 * 4 * 64;
        Qs[base + sc]       = qv.x * scale;
        Qs[base + 64 + sc]  = qv.y * scale;
        Qs[base + 128 + sc] = qv.z * scale;
        Qs[base + 192 + sc] = qv.w * scale;
    }

    u64 racc[4][4];
#pragma unroll
    for (int i = 0; i < 4; i++)
#pragma unroll
        for (int j = 0; j < 4; j++) racc[i][j] = 0ull;
    float rmax[4] = {-1e30f, -1e30f, -1e30f, -1e30f};
    float rsum[4] = {0.f, 0.f, 0.f, 0.f};

    for (int kt = 0; kt < 16; kt++) {
        __syncthreads();  // prev PV done (and Q ready on iter 0)
        const int kbase = b * 1024 + kt * 64;
#pragma unroll
        for (int it = 0; it < 8; it++) {
            int slot = it * 256 + tid;
            int row = slot >> 5, d4 = slot & 31;
            const float* src = g_qkv + (size_t)(kbase + row) * 1536 + h * 384 + d4 * 4;
            float4 kv = *(const float4*)(src + 128);
            float4 vv = *(const float4*)(src + 256);
            int sc = row ^ (d4 * 2);
            int base = d4 * 4 * 64;
            Ks[base + sc]       = kv.x;
            Ks[base + 64 + sc]  = kv.y;
            Ks[base + 128 + sc] = kv.z;
            Ks[base + 192 + sc] = kv.w;
            *(float4*)&Vs[row * 128 + d4 * 4] = vv;
        }
        __syncthreads();

        // S[64x64] = Q K^T (pre-scaled); swizzle group g constant per 4 d's.
        u64 sp[4][2];
#pragma unroll
        for (int i = 0; i < 4; i++) { sp[i][0] = 0ull; sp[i][1] = 0ull; }
#pragma unroll 2
        for (int dg = 0; dg < 32; dg++) {
            const int g = dg * 2;
            const float* qrow = Qs + dg * 256;
            const float* krow = Ks + dg * 256;
            const int oq0 = (2 * ty) ^ g, oq1 = (32 + 2 * ty) ^ g;
            const int ok0 = (2 * tx) ^ g, ok1 = (32 + 2 * tx) ^ g;
#pragma unroll
            for (int dd = 0; dd < 4; dd++) {
                float2 qa0 = *(const float2*)(qrow + dd * 64 + oq0);
                float2 qa1 = *(const float2*)(qrow + dd * 64 + oq1);
                u64 kb0 = *(const u64*)(krow + dd * 64 + ok0);
                u64 kb1 = *(const u64*)(krow + dd * 64 + ok1);
                u64 a;
                a = dup2(qa0.x); fma2(sp[0][0], a, kb0); fma2(sp[0][1], a, kb1);
                a = dup2(qa0.y); fma2(sp[1][0], a, kb0); fma2(sp[1][1], a, kb1);
                a = dup2(qa1.x); fma2(sp[2][0], a, kb0); fma2(sp[2][1], a, kb1);
                a = dup2(qa1.y); fma2(sp[3][0], a, kb0); fma2(sp[3][1], a, kb1);
            }
        }

        // online softmax + write P transposed
        const int cols[4] = {2 * tx, 2 * tx + 1, 32 + 2 * tx, 33 + 2 * tx};
        const int rows[4] = {2 * ty, 2 * ty + 1, 32 + 2 * ty, 33 + 2 * ty};
#pragma unroll
        for (int i = 0; i < 4; i++) {
            float2 p0 = u2f(sp[i][0]), p1 = u2f(sp[i][1]);
            float s0 = p0.x, s1 = p0.y, s2 = p1.x, s3 = p1.y;
            float tmax = red16max(fmaxf(fmaxf(s0, s1), fmaxf(s2, s3)));
            float mnew = fmaxf(rmax[i], tmax);
            float corr = __expf(rmax[i] - mnew);
            rmax[i] = mnew;
            float e0 = __expf(s0 - mnew), e1 = __expf(s1 - mnew);
            float e2 = __expf(s2 - mnew), e3 = __expf(s3 - mnew);
            rsum[i] = rsum[i] * corr + red16sum(e0 + e1 + e2 + e3);
            u64 c2 = dup2(corr);
            racc[i][0] = mul2(racc[i][0], c2);
            racc[i][1] = mul2(racc[i][1], c2);
            racc[i][2] = mul2(racc[i][2], c2);
            racc[i][3] = mul2(racc[i][3], c2);
            int r = rows[i];
            Ps[cols[0] * 64 + (r ^ ((cols[0] >> 2) << 1))] = e0;
            Ps[cols[1] * 64 + (r ^ ((cols[1] >> 2) << 1))] = e1;
            Ps[cols[2] * 64 + (r ^ ((cols[2] >> 2) << 1))] = e2;
            Ps[cols[3] * 64 + (r ^ ((cols[3] >> 2) << 1))] = e3;
        }
        __syncthreads();

        // O[64x128] += P V ; swizzle group g constant per 4 j's.
#pragma unroll 2
        for (int jg = 0; jg < 16; jg++) {
            const int g = jg * 2;
            const float* prow = Ps + jg * 256;
            const float* vrow = Vs + jg * 512 + tx * 4;
            const int op0 = (2 * ty) ^ g, op1 = (32 + 2 * ty) ^ g;
#pragma unroll
            for (int jj = 0; jj < 4; jj++) {
                float2 pa0 = *(const float2*)(prow + jj * 64 + op0);
                float2 pa1 = *(const float2*)(prow + jj * 64 + op1);
                ulonglong2 v0 = *(const ulonglong2*)(vrow + jj * 128);
                ulonglong2 v1 = *(const ulonglong2*)(vrow + jj * 128 + 64);
                u64 a;
                a = dup2(pa0.x); fma2(racc[0][0], a, v0.x); fma2(racc[0][1], a, v0.y);
                                 fma2(racc[0][2], a, v1.x); fma2(racc[0][3], a, v1.y);
                a = dup2(pa0.y); fma2(racc[1][0], a, v0.x); fma2(racc[1][1], a, v0.y);
                                 fma2(racc[1][2], a, v1.x); fma2(racc[1][3], a, v1.y);
                a = dup2(pa1.x); fma2(racc[2][0], a, v0.x); fma2(racc[2][1], a, v0.y);
                                 fma2(racc[2][2], a, v1.x); fma2(racc[2][3], a, v1.y);
                a = dup2(pa1.y); fma2(racc[3][0], a, v0.x); fma2(racc[3][1], a, v0.y);
                                 fma2(racc[3][2], a, v1.x); fma2(racc[3][3], a, v1.y);
            }
        }
    }

    // normalize + write transposed: g_attT[(h*128+d)*8192 + token], float2 pairs
    float inv0 = 1.0f / rsum[0], inv1 = 1.0f / rsum[1];
    float inv2 = 1.0f / rsum[2], inv3 = 1.0f / rsum[3];
#pragma unroll
    for (int j = 0; j < 4; j++) {
        int d0 = (j < 2) ? (tx * 4 + j * 2) : (64 + tx * 4 + (j - 2) * 2);
        float2 a = u2f(racc[0][j]);  // row 2ty,    d0 / d0+1
        float2 c = u2f(racc[1][j]);  // row 2ty+1
        float2 e = u2f(racc[2][j]);  // row 32+2ty
        float2 f = u2f(racc[3][j]);  // row 33+2ty
        size_t base0 = (size_t)(h * 128 + d0) * 8192 + tok0;
        size_t base1 = base0 + 8192;
        *(float2*)(g_attT + base0 + 2 * ty)      = make_float2(a.x * inv0, c.x * inv1);
        *(float2*)(g_attT + base1 + 2 * ty)      = make_float2(a.y * inv0, c.y * inv1);
        *(float2*)(g_attT + base0 + 32 + 2 * ty) = make_float2(e.x * inv2, f.x * inv3);
        *(float2*)(g_attT + base1 + 32 + 2 * ty) = make_float2(e.y * inv2, f.y * inv3);
    }
}

// ============================================================================
// Kernel 3: out[b][c][pos] = (attn @ Wo)[m][c] + bo[c] + xs[m][c], computed as
// C^T[c][tok]; R6-proven LDG/STS path, minBlocks=2.
// ============================================================================
__global__ void __launch_bounds__(256, 2) out_kernel(const float* __restrict__ x,
                                                     const float* __restrict__ Wo,
                                                     const float* __restrict__ bo,
                                                     float* __restrict__ out) {
    __shared__ float As[16][128];  // Wo[k][c] slice (contiguous in c)
    __shared__ float Bs[16][128];  // g_attT[k][tok] slice (contiguous in tok)
    const int tid = threadIdx.x;
    const int tx = tid & 15, ty = tid >> 4;
    const int c0 = blockIdx.x * 128;
    const int m0 = blockIdx.y * 128;
    const int b = m0 >> 10;
    const int pos0 = m0 & 1023;

    u64 acc[8][4];
#pragma unroll
    for (int i = 0; i < 8; i++)
#pragma unroll
        for (int j = 0; j < 4; j++) acc[i][j] = 0ull;

    for (int k0 = 0; k0 < 512; k0 += 16) {
        __syncthreads();
#pragma unroll
        for (int it = 0; it < 2; it++) {
            int slot = it * 256 + tid;
            int kk = slot >> 5, q4 = slot & 31;
            *(float4*)&As[kk][q4 * 4] = *(const float4*)(Wo + (size_t)(k0 + kk) * 512 + c0 + q4 * 4);
            *(float4*)&Bs[kk][q4 * 4] = *(const float4*)(g_attT + (size_t)(k0 + kk) * 8192 + m0 + q4 * 4);
        }
        __syncthreads();
#pragma unroll
        for (int kk = 0; kk < 16; kk++) {
            float4 a0 = *(const float4*)&As[kk][ty * 4];
            float4 a1 = *(const float4*)&As[kk][64 + ty * 4];
            ulonglong2 b0 = *(const ulonglong2*)&Bs[kk][tx * 4];
            ulonglong2 b1 = *(const ulonglong2*)&Bs[kk][64 + tx * 4];
            float am[8] = {a0.x, a0.y, a0.z, a0.w, a1.x, a1.y, a1.z, a1.w};
#pragma unroll
            for (int i = 0; i < 8; i++) {
                u64 ad = dup2(am[i]);
                fma2(acc[i][0], ad, b0.x);
                fma2(acc[i][1], ad, b0.y);
                fma2(acc[i][2], ad, b1.x);
                fma2(acc[i][3], ad, b1.y);
            }
        }
    }
#pragma unroll
    for (int i = 0; i < 8; i++) {
        int c = c0 + ((i < 4) ? (ty * 4 + i) : (64 + ty * 4 + i - 4));
        float bb = bo[c];
        const float* xr = x + ((size_t)b * 512 + c) * 1024 + pos0;
        float* orow = out + ((size_t)b * 512 + c) * 1024 + pos0;
        float4 r0 = *(const float4*)(xr + tx * 4);
        float4 r1 = *(const float4*)(xr + 64 + tx * 4);
        float2 p0 = u2f(acc[i][0]), p1 = u2f(acc[i][1]);
        float2 p2 = u2f(acc[i][2]), p3 = u2f(acc[i][3]);
        *(float4*)(orow + tx * 4) =
            make_float4(p0.x + bb + r0.x, p0.y + bb + r0.y, p1.x + bb + r0.z, p1.y + bb + r0.w);
        *(float4*)(orow + 64 + tx * 4) =
            make_float4(p2.x + bb + r1.x, p2.y + bb + r1.y, p3.x + bb + r1.z, p3.y + bb + r1.w);
    }
}

extern "C" void kernel_launch(void* const* d_in, const int* in_sizes, int n_in,
                              void* d_out, int out_size) {
    const float* x  = (const float*)d_in[0];
    const float* Wp = (const float*)d_in[1];
    const float* bp = (const float*)d_in[2];
    const float* Wo = (const float*)d_in[3];
    const float* bo = (const float*)d_in[4];
    float* out = (float*)d_out;

    static bool attr_set = false;
    if (!attr_set) {
        cudaFuncSetAttribute(attn_kernel, cudaFuncAttributeMaxDynamicSharedMemorySize, ATTN_SMEM);
        attr_set = true;
    }

    qkv_kernel<<<dim3(12, 64), 256>>>(x, Wp, bp);
    attn_kernel<<<dim3(16, 4, 8), 256, ATTN_SMEM>>>();
    out_kernel<<<dim3(4, 64), 256>>>(x, Wo, bo, out);
}

// round 17
// speedup vs baseline: 1.7952x; 1.1444x over previous
#include <cuda_runtime.h>
#include <cstdint>
#include <cstddef>

typedef unsigned long long u64;
#define DEVINL __device__ __forceinline__

DEVINL u64 dup2(float v) { u64 r; asm("mov.b64 %0, {%1, %1};" : "=l"(r) : "f"(v)); return r; }
DEVINL float2 u2f(u64 v) { float2 f; asm("mov.b64 {%0, %1}, %2;" : "=f"(f.x), "=f"(f.y) : "l"(v)); return f; }
DEVINL void fma2(u64& d, u64 a, u64 b) { asm("fma.rn.f32x2 %0, %1, %2, %0;" : "+l"(d) : "l"(a), "l"(b)); }
DEVINL u64 mul2(u64 a, u64 b) { u64 d; asm("mul.rn.f32x2 %0, %1, %2;" : "=l"(d) : "l"(a), "l"(b)); return d; }
DEVINL float red16max(float v) {
    v = fmaxf(v, __shfl_xor_sync(~0u, v, 1)); v = fmaxf(v, __shfl_xor_sync(~0u, v, 2));
    v = fmaxf(v, __shfl_xor_sync(~0u, v, 4)); v = fmaxf(v, __shfl_xor_sync(~0u, v, 8)); return v;
}
DEVINL float red16sum(float v) {
    v += __shfl_xor_sync(~0u, v, 1); v += __shfl_xor_sync(~0u, v, 2);
    v += __shfl_xor_sync(~0u, v, 4); v += __shfl_xor_sync(~0u, v, 8); return v;
}

DEVINL unsigned pack_bf16x2(float f0, float f1) {  // low half = f0 (k), high = f1 (k+1)
    unsigned r; asm("cvt.rn.bf16x2.f32 %0, %1, %2;" : "=r"(r) : "f"(f1), "f"(f0)); return r;
}
DEVINL float lo_f(unsigned p) { return __uint_as_float(p << 16); }
DEVINL float hi_f(unsigned p) { return __uint_as_float(p & 0xffff0000u); }

DEVINL void mma16816(float4& d, const uint32_t* a, const uint32_t* b) {
    asm volatile("mma.sync.aligned.m16n8k16.row.col.f32.bf16.bf16.f32 "
        "{%0,%1,%2,%3}, {%4,%5,%6,%7}, {%8,%9}, {%0,%1,%2,%3};"
        : "+f"(d.x), "+f"(d.y), "+f"(d.z), "+f"(d.w)
        : "r"(a[0]), "r"(a[1]), "r"(a[2]), "r"(a[3]), "r"(b[0]), "r"(b[1]));
}

__device__ float g_qkv[8192ull * 1536ull];   // [token][h*384 + {q,k,v} + d]
__device__ float g_attT[512ull * 8192ull];   // [c][token]

// ---- mma.sync GEMM: D[128 x 128] = A[128 x 512] . B[128 x 512]^T, bf16x3 ----
// smem: 4 tiles of [128 rows][64 k] bf16, XOR-8 swizzled: elem (r,k) at r*64 + (k ^ ((r&7)<<3))
#define GEMM_SMEM (4 * 16384)

DEVINL uint32_t lds32(const unsigned short* s, int row, int k) {
    return *(const unsigned*)&s[row * 64 + (k ^ ((row & 7) << 3))];
}

// load rows r,r+1 (16 k's of quarter kq) from MN-major gmem (elem [k][row] at src + k*rs + row)
DEVINL void load_tile(const float* __restrict__ src, int rs, int kb,
                      unsigned short* sH, unsigned short* sL, int r, int kq, int gid) {
    const float* s0 = src + (size_t)(kb + kq * 16) * rs + r;
    const int sw0 = (r & 7) << 3, sw1 = ((r + 1) & 7) << 3;
#pragma unroll
    for (int i = 0; i < 8; i++) {
        int ip = (i + gid) & 7;
        int k = 2 * ip;                 // k within quarter
        float2 fa = *(const float2*)(s0 + (size_t)k * rs);
        float2 fb = *(const float2*)(s0 + (size_t)(k + 1) * rs);
        int kg = kq * 16 + k;
        unsigned ph0 = pack_bf16x2(fa.x, fb.x), ph1 = pack_bf16x2(fa.y, fb.y);
        unsigned pl0 = pack_bf16x2(fa.x - lo_f(ph0), fb.x - hi_f(ph0));
        unsigned pl1 = pack_bf16x2(fa.y - lo_f(ph1), fb.y - hi_f(ph1));
        int o0 = r * 64 + (kg ^ sw0), o1 = (r + 1) * 64 + (kg ^ sw1);
        *(unsigned*)&sH[o0] = ph0; *(unsigned*)&sH[o1] = ph1;
        *(unsigned*)&sL[o0] = pl0; *(unsigned*)&sL[o1] = pl1;
    }
}

DEVINL void gemm_mma(const float* __restrict__ srcA, int rsA,
                     const float* __restrict__ srcB, int rsB, float4 (&acc)[4][4]) {
    extern __shared__ unsigned short smb[];
    unsigned short* sAH = smb;
    unsigned short* sAL = smb + 8192;
    unsigned short* sBH = smb + 16384;
    unsigned short* sBL = smb + 24576;
    const int tid = threadIdx.x, lane = tid & 31, warp = tid >> 5;
    const int gid = lane >> 2, tig = lane & 3;
    const int r = 2 * (tid & 63), kq = tid >> 6;
    const int wm = warp & 1, wn = warp >> 1;   // warp tile: 64m x 32n
#pragma unroll
    for (int mi = 0; mi < 4; mi++)
#pragma unroll
        for (int ni = 0; ni < 4; ni++) acc[mi][ni] = make_float4(0.f, 0.f, 0.f, 0.f);

    for (int blk = 0; blk < 8; blk++) {
        __syncthreads();
        load_tile(srcA, rsA, blk * 64, sAH, sAL, r, kq, gid);
        load_tile(srcB, rsB, blk * 64, sBH, sBL, r, kq, gid);
        __syncthreads();
#pragma unroll
        for (int ks = 0; ks < 4; ks++) {
            const int kk = ks * 16 + tig * 2;
            uint32_t ah[4][4], al[4][4], bh[4][2], bl[4][2];
#pragma unroll
            for (int mi = 0; mi < 4; mi++) {
                int row = wm * 64 + mi * 16 + gid;
                ah[mi][0] = lds32(sAH, row, kk);     ah[mi][1] = lds32(sAH, row + 8, kk);
                ah[mi][2] = lds32(sAH, row, kk + 8); ah[mi][3] = lds32(sAH, row + 8, kk + 8);
                al[mi][0] = lds32(sAL, row, kk);     al[mi][1] = lds32(sAL, row + 8, kk);
                al[mi][2] = lds32(sAL, row, kk + 8); al[mi][3] = lds32(sAL, row + 8, kk + 8);
            }
#pragma unroll
            for (int ni = 0; ni < 4; ni++) {
                int n = wn * 32 + ni * 8 + gid;
                bh[ni][0] = lds32(sBH, n, kk); bh[ni][1] = lds32(sBH, n, kk + 8);
                bl[ni][0] = lds32(sBL, n, kk); bl[ni][1] = lds32(sBL, n, kk + 8);
            }
#pragma unroll
            for (int mi = 0; mi < 4; mi++)
#pragma unroll
                for (int ni = 0; ni < 4; ni++) {
                    mma16816(acc[mi][ni], ah[mi], bh[ni]);
                    mma16816(acc[mi][ni], ah[mi], bl[ni]);
                    mma16816(acc[mi][ni], al[mi], bh[ni]);
                }
        }
    }
}

// qkv = xs @ Wp + bp.  A[token][k]: x is [k][token] (rs=1024); B[n][k]: Wp is [k][n] (rs=1536).
__global__ void __launch_bounds__(256) qkv_mma_kernel(const float* __restrict__ x,
                                                      const float* __restrict__ Wp,
                                                      const float* __restrict__ bp) {
    const int n0 = blockIdx.x * 128, m0 = blockIdx.y * 128;
    const int b = m0 >> 10, pos0 = m0 & 1023;
    float4 acc[4][4];
    gemm_mma(x + (size_t)b * (512 * 1024) + pos0, 1024, Wp + n0, 1536, acc);
    const int lane = threadIdx.x & 31, warp = threadIdx.x >> 5;
    const int gid = lane >> 2, tig = lane & 3;
    const int wm = warp & 1, wn = warp >> 1;
#pragma unroll
    for (int mi = 0; mi < 4; mi++) {
        int token = m0 + wm * 64 + mi * 16 + gid;
#pragma unroll
        for (int ni = 0; ni < 4; ni++) {
            int col = n0 + wn * 32 + ni * 8 + tig * 2;
            float2 bv = *(const float2*)(bp + col);
            float4 a = acc[mi][ni];
            *(float2*)&g_qkv[(size_t)token * 1536 + col] = make_float2(a.x + bv.x, a.y + bv.y);
            *(float2*)&g_qkv[(size_t)(token + 8) * 1536 + col] = make_float2(a.z + bv.x, a.w + bv.y);
        }
    }
}

// out^T[c][tok] = Wo^T.attT + bo + x.  A[c][k]: Wo is [k][c] (rs=512); B[tok][k]: attT (rs=8192).
__global__ void __launch_bounds__(256) out_mma_kernel(const float* __restrict__ x,
                                                      const float* __restrict__ Wo,
                                                      const float* __restrict__ bo,
                                                      float* __restrict__ out) {
    const int c0 = blockIdx.x * 128, n0 = blockIdx.y * 128;
    float4 acc[4][4];
    gemm_mma(Wo + c0, 512, g_attT + n0, 8192, acc);
    const int lane = threadIdx.x & 31, warp = threadIdx.x >> 5;
    const int gid = lane >> 2, tig = lane & 3;
    const int wm = warp & 1, wn = warp >> 1;
    const int b = n0 >> 10, pos0 = n0 & 1023;
#pragma unroll
    for (int mi = 0; mi < 4; mi++) {
        int c = c0 + wm * 64 + mi * 16 + gid;
        float bb0 = bo[c], bb8 = bo[c + 8];
#pragma unroll
        for (int ni = 0; ni < 4; ni++) {
            int pos = pos0 + wn * 32 + ni * 8 + tig * 2;
            size_t o0 = ((size_t)(b * 512 + c)) * 1024 + pos;
            size_t o8 = o0 + 8 * 1024;
            float2 r0 = *(const float2*)(x + o0);
            float2 r8 = *(const float2*)(x + o8);
            float4 a = acc[mi][ni];
            *(float2*)(out + o0) = make_float2(a.x + bb0 + r0.x, a.y + bb0 + r0.y);
            *(float2*)(out + o8) = make_float2(a.z + bb8 + r8.x, a.w + bb8 + r8.y);
        }
    }
}

// ---------------- attention: unchanged proven R8 scalar kernel ----------------
#define ATTN_SMEM (28672 * 4)
__global__ void __launch_bounds__(256, 2) attn_kernel() {
    extern __shared__ float sm[];
    float* Qs = sm; float* Ks = sm + 8192; float* Vs = sm + 16384; float* Ps = sm + 24576;
    const int tid = threadIdx.x, tx = tid & 15, ty = tid >> 4;
    const int qt = blockIdx.x, h = blockIdx.y, b = blockIdx.z;
    const int tok0 = b * 1024 + qt * 64;
    const float scale = 0.08838834764831845f;
#pragma unroll
    for (int it = 0; it < 8; it++) {
        int slot = it * 256 + tid, row = slot >> 5, d4 = slot & 31;
        float4 qv = *(const float4*)(g_qkv + (size_t)(tok0 + row) * 1536 + h * 384 + d4 * 4);
        int sc = row ^ (d4 * 2); int base = d4 * 4 * 64;
        Qs[base + sc] = qv.x * scale; Qs[base + 64 + sc] = qv.y * scale;
        Qs[base + 128 + sc] = qv.z * scale; Qs[base + 192 + sc] = qv.w * scale;
    }
    u64 racc[4][4];
#pragma unroll
    for (int i = 0; i < 4; i++)
#pragma unroll
        for (int j = 0; j < 4; j++) racc[i][j] = 0ull;
    float rmax[4] = {-1e30f, -1e30f, -1e30f, -1e30f};
    float rsum[4] = {0.f, 0.f, 0.f, 0.f};
    for (int kt = 0; kt < 16; kt++) {
        __syncthreads();
        const int kbase = b * 1024 + kt * 64;
#pragma unroll
        for (int it = 0; it < 8; it++) {
            int slot = it * 256 + tid, row = slot >> 5, d4 = slot & 31;
            const float* src = g_qkv + (size_t)(kbase + row) * 1536 + h * 384 + d4 * 4;
            float4 kv = *(const float4*)(src + 128);
            float4 vv = *(const float4*)(src + 256);
            int sc = row ^ (d4 * 2); int base = d4 * 4 * 64;
            Ks[base + sc] = kv.x; Ks[base + 64 + sc] = kv.y;
            Ks[base + 128 + sc] = kv.z; Ks[base + 192 + sc] = kv.w;
            *(float4*)&Vs[row * 128 + d4 * 4] = vv;
        }
        __syncthreads();
        u64 sp[4][2];
#pragma unroll
        for (int i = 0; i < 4; i++) { sp[i][0] = 0ull; sp[i][1] = 0ull; }
#pragma unroll 2
        for (int dg = 0; dg < 32; dg++) {
            const int g = dg * 2;
            const float* qrow = Qs + dg * 256; const float* krow = Ks + dg * 256;
            const int oq0 = (2 * ty) ^ g, oq1 = (32 + 2 * ty) ^ g;
            const int ok0 = (2 * tx) ^ g, ok1 = (32 + 2 * tx) ^ g;
#pragma unroll
            for (int dd = 0; dd < 4; dd++) {
                float2 qa0 = *(const float2*)(qrow + dd * 64 + oq0);
                float2 qa1 = *(const float2*)(qrow + dd * 64 + oq1);
                u64 kb0 = *(const u64*)(krow + dd * 64 + ok0);
                u64 kb1 = *(const u64*)(krow + dd * 64 + ok1);
                u64 a;
                a = dup2(qa0.x); fma2(sp[0][0], a, kb0); fma2(sp[0][1], a, kb1);
                a = dup2(qa0.y); fma2(sp[1][0], a, kb0); fma2(sp[1][1], a, kb1);
                a = dup2(qa1.x); fma2(sp[2][0], a, kb0); fma2(sp[2][1], a, kb1);
                a = dup2(qa1.y); fma2(sp[3][0], a, kb0); fma2(sp[3][1], a, kb1);
            }
        }
        const int cols[4] = {2 * tx, 2 * tx + 1, 32 + 2 * tx, 33 + 2 * tx};
        const int rows[4] = {2 * ty, 2 * ty + 1, 32 + 2 * ty, 33 + 2 * ty};
#pragma unroll
        for (int i = 0; i < 4; i++) {
            float2 p0 = u2f(sp[i][0]), p1 = u2f(sp[i][1]);
            float s0 = p0.x, s1 = p0.y, s2 = p1.x, s3 = p1.y;
            float tmax = red16max(fmaxf(fmaxf(s0, s1), fmaxf(s2, s3)));
            float mnew = fmaxf(rmax[i], tmax);
            float corr = __expf(rmax[i] - mnew);
            rmax[i] = mnew;
            float e0 = __expf(s0 - mnew), e1 = __expf(s1 - mnew);
            float e2 = __expf(s2 - mnew), e3 = __expf(s3 - mnew);
            rsum[i] = rsum[i] * corr + red16sum(e0 + e1 + e2 + e3);
            u64 c2 = dup2(corr);
            racc[i][0] = mul2(racc[i][0], c2); racc[i][1] = mul2(racc[i][1], c2);
            racc[i][2] = mul2(racc[i][2], c2); racc[i][3] = mul2(racc[i][3], c2);
            int r = rows[i];
            Ps[cols[0] * 64 + (r ^ ((cols[0] >> 2) << 1))] = e0;
            Ps[cols[1] * 64 + (r ^ ((cols[1] >> 2) << 1))] = e1;
            Ps[cols[2] * 64 + (r ^ ((cols[2] >> 2) << 1))] = e2;
            Ps[cols[3] * 64 + (r ^ ((cols[3] >> 2) << 1))] = e3;
        }
        __syncthreads();
#pragma unroll 2
        for (int jg = 0; jg < 16; jg++) {
            const int g = jg * 2;
            const float* prow = Ps + jg * 256; const float* vrow = Vs + jg * 512 + tx * 4;
            const int op0 = (2 * ty) ^ g, op1 = (32 + 2 * ty) ^ g;
#pragma unroll
            for (int jj = 0; jj < 4; jj++) {
                float2 pa0 = *(const float2*)(prow + jj * 64 + op0);
                float2 pa1 = *(const float2*)(prow + jj * 64 + op1);
                ulonglong2 v0 = *(const ulonglong2*)(vrow + jj * 128);
                ulonglong2 v1 = *(const ulonglong2*)(vrow + jj * 128 + 64);
                u64 a;
                a = dup2(pa0.x); fma2(racc[0][0], a, v0.x); fma2(racc[0][1], a, v0.y); fma2(racc[0][2], a, v1.x); fma2(racc[0][3], a, v1.y);
                a = dup2(pa0.y); fma2(racc[1][0], a, v0.x); fma2(racc[1][1], a, v0.y); fma2(racc[1][2], a, v1.x); fma2(racc[1][3], a, v1.y);
                a = dup2(pa1.x); fma2(racc[2][0], a, v0.x); fma2(racc[2][1], a, v0.y); fma2(racc[2][2], a, v1.x); fma2(racc[2][3], a, v1.y);
                a = dup2(pa1.y); fma2(racc[3][0], a, v0.x); fma2(racc[3][1], a, v0.y); fma2(racc[3][2], a, v1.x); fma2(racc[3][3], a, v1.y);
            }
        }
    }
    float inv0 = 1.0f / rsum[0], inv1 = 1.0f / rsum[1];
    float inv2 = 1.0f / rsum[2], inv3 = 1.0f / rsum[3];
#pragma unroll
    for (int j = 0; j < 4; j++) {
        int d0 = (j < 2) ? (tx * 4 + j * 2) : (64 + tx * 4 + (j - 2) * 2);
        float2 a = u2f(racc[0][j]), c = u2f(racc[1][j]);
        float2 e = u2f(racc[2][j]), f = u2f(racc[3][j]);
        size_t base0 = (size_t)(h * 128 + d0) * 8192 + tok0, base1 = base0 + 8192;
        *(float2*)(g_attT + base0 + 2 * ty)      = make_float2(a.x * inv0, c.x * inv1);
        *(float2*)(g_attT + base1 + 2 * ty)      = make_float2(a.y * inv0, c.y * inv1);
        *(float2*)(g_attT + base0 + 32 + 2 * ty) = make_float2(e.x * inv2, f.x * inv3);
        *(float2*)(g_attT + base1 + 32 + 2 * ty) = make_float2(e.y * inv2, f.y * inv3);
    }
}

extern "C" void kernel_launch(void* const* d_in, const int* in_sizes, int n_in,
                              void* d_out, int out_size) {
    const float* x  = (const float*)d_in[0];
    const float* Wp = (const float*)d_in[1];
    const float* bp = (const float*)d_in[2];
    const float* Wo = (const float*)d_in[3];
    const float* bo = (const float*)d_in[4];
    float* out = (float*)d_out;
    static bool attr_set = false;
    if (!attr_set) {
        cudaFuncSetAttribute(attn_kernel,     cudaFuncAttributeMaxDynamicSharedMemorySize, ATTN_SMEM);
        cudaFuncSetAttribute(qkv_mma_kernel,  cudaFuncAttributeMaxDynamicSharedMemorySize, GEMM_SMEM);
        cudaFuncSetAttribute(out_mma_kernel,  cudaFuncAttributeMaxDynamicSharedMemorySize, GEMM_SMEM);
        attr_set = true;
    }
    qkv_mma_kernel<<<dim3(12, 64), 256, GEMM_SMEM>>>(x, Wp, bp);
    attn_kernel<<<dim3(16, 4, 8), 256, ATTN_SMEM>>>();
    out_mma_kernel<<<dim3(4, 64), 256, GEMM_SMEM>>>(x, Wo, bo, out);
}